// round 1
// baseline (speedup 1.0000x reference)
#include <cuda_runtime.h>
#include <cstdint>

// Problem constants (from reference: B=2, N=131072, M=512, G=20)
#define BB 2
#define NN 131072
#define MM 512
#define GG 20
#define VV (GG * GG * GG)          // 8000 voxels per batch
#define VOXINV 2.0f                 // 1 / 0.5 voxel size

// Device scratch (no allocations allowed in kernel_launch)
__device__ unsigned int  g_minc[BB * 3];          // min coords as monotonic uint bits
__device__ unsigned char g_mask[BB * VV];         // voxel needed?
__device__ float         g_acc[BB * VV * 10];     // cnt, sx, sy, sz, xx, xy, xz, yy, yz, zz

// ---------------------------------------------------------------------------
// K0: reset per-replay state: min coords -> +inf bits, mask -> 0.
// (acc is zeroed lazily in K2 only for needed voxels.)
// ---------------------------------------------------------------------------
__global__ void k_init() {
    int t = blockIdx.x * blockDim.x + threadIdx.x;
    if (t < BB * 3) g_minc[t] = 0x7F800000u;  // +inf bit pattern
    // zero mask: BB*VV = 16000 bytes = 1000 uint4
    uint4* m4 = reinterpret_cast<uint4*>(g_mask);
    for (int j = t; j < (BB * VV) / 16; j += gridDim.x * blockDim.x)
        m4[j] = make_uint4(0u, 0u, 0u, 0u);
}

// ---------------------------------------------------------------------------
// K1: per-batch coordinate-wise min over N points.
// grid = (blocksX, BB). Positive floats -> uint bit order == float order.
// ---------------------------------------------------------------------------
__global__ void k_min(const float* __restrict__ x) {
    int b = blockIdx.y;
    float m0 = 3.0e38f, m1 = 3.0e38f, m2 = 3.0e38f;
    const float* xb = x + (size_t)b * NN * 3;
    for (int i = blockIdx.x * blockDim.x + threadIdx.x; i < NN;
         i += gridDim.x * blockDim.x) {
        m0 = fminf(m0, __ldg(xb + i * 3 + 0));
        m1 = fminf(m1, __ldg(xb + i * 3 + 1));
        m2 = fminf(m2, __ldg(xb + i * 3 + 2));
    }
#pragma unroll
    for (int o = 16; o > 0; o >>= 1) {
        m0 = fminf(m0, __shfl_xor_sync(0xFFFFFFFFu, m0, o));
        m1 = fminf(m1, __shfl_xor_sync(0xFFFFFFFFu, m1, o));
        m2 = fminf(m2, __shfl_xor_sync(0xFFFFFFFFu, m2, o));
    }
    if ((threadIdx.x & 31) == 0) {
        atomicMin(&g_minc[b * 3 + 0], __float_as_uint(m0));
        atomicMin(&g_minc[b * 3 + 1], __float_as_uint(m1));
        atomicMin(&g_minc[b * 3 + 2], __float_as_uint(m2));
    }
}

__device__ __forceinline__ int voxel_of(float px, float py, float pz,
                                        float n0, float n1, float n2) {
    int vx = (int)floorf((px - n0) * VOXINV);
    int vy = (int)floorf((py - n1) * VOXINV);
    int vz = (int)floorf((pz - n2) * VOXINV);
    vx = min(max(vx, 0), GG - 1);
    vy = min(max(vy, 0), GG - 1);
    vz = min(max(vz, 0), GG - 1);
    return (vx * GG + vy) * GG + vz;
}

// ---------------------------------------------------------------------------
// K2: mark voxels needed by sampled points; lazily zero their accumulators.
// ---------------------------------------------------------------------------
__global__ void k_mark(const float* __restrict__ x, const int* __restrict__ sidx) {
    int t = blockIdx.x * blockDim.x + threadIdx.x;
    if (t >= BB * MM) return;
    int b = t / MM;
    int i = sidx[t];
    const float* p = x + ((size_t)b * NN + i) * 3;
    float n0 = __uint_as_float(g_minc[b * 3 + 0]);
    float n1 = __uint_as_float(g_minc[b * 3 + 1]);
    float n2 = __uint_as_float(g_minc[b * 3 + 2]);
    int v = voxel_of(p[0], p[1], p[2], n0, n1, n2);
    int gi = b * VV + v;
    g_mask[gi] = 1;                       // idempotent
    float* a = &g_acc[(size_t)gi * 10];
#pragma unroll
    for (int k = 0; k < 10; k++) a[k] = 0.0f;  // idempotent zero (pre-K3)
}

// ---------------------------------------------------------------------------
// K3: accumulate count/sum/outer for points landing in needed voxels only.
// ~6% of points pass the mask -> ~330k spread atomics total.
// ---------------------------------------------------------------------------
__global__ void k_accum(const float* __restrict__ x) {
    int t = blockIdx.x * blockDim.x + threadIdx.x;
    if (t >= BB * NN) return;
    int b = t >> 17;  // / NN (NN = 2^17)
    const float* p = x + (size_t)t * 3;
    float px = __ldg(p + 0), py = __ldg(p + 1), pz = __ldg(p + 2);
    float n0 = __uint_as_float(g_minc[b * 3 + 0]);
    float n1 = __uint_as_float(g_minc[b * 3 + 1]);
    float n2 = __uint_as_float(g_minc[b * 3 + 2]);
    int v = voxel_of(px, py, pz, n0, n1, n2);
    int gi = b * VV + v;
    if (!g_mask[gi]) return;
    float* a = &g_acc[(size_t)gi * 10];
    atomicAdd(a + 0, 1.0f);
    atomicAdd(a + 1, px);
    atomicAdd(a + 2, py);
    atomicAdd(a + 3, pz);
    atomicAdd(a + 4, px * px);
    atomicAdd(a + 5, px * py);
    atomicAdd(a + 6, px * pz);
    atomicAdd(a + 7, py * py);
    atomicAdd(a + 8, py * pz);
    atomicAdd(a + 9, pz * pz);
}

// ---------------------------------------------------------------------------
// K4: gather stats at sampled voxels, finalize mean + covariance (B, M, 12).
// ---------------------------------------------------------------------------
__global__ void k_out(const float* __restrict__ x, const int* __restrict__ sidx,
                      float* __restrict__ out) {
    int t = blockIdx.x * blockDim.x + threadIdx.x;
    if (t >= BB * MM) return;
    int b = t / MM;
    int i = sidx[t];
    const float* p = x + ((size_t)b * NN + i) * 3;
    float n0 = __uint_as_float(g_minc[b * 3 + 0]);
    float n1 = __uint_as_float(g_minc[b * 3 + 1]);
    float n2 = __uint_as_float(g_minc[b * 3 + 2]);
    int v = voxel_of(p[0], p[1], p[2], n0, n1, n2);
    const float* a = &g_acc[(size_t)(b * VV + v) * 10];

    float safe = fmaxf(a[0], 1.0f);
    float inv = 1.0f / safe;
    float mx = a[1] * inv, my = a[2] * inv, mz = a[3] * inv;
    float cxx = a[4] * inv - mx * mx;
    float cxy = a[5] * inv - mx * my;
    float cxz = a[6] * inv - mx * mz;
    float cyy = a[7] * inv - my * my;
    float cyz = a[8] * inv - my * mz;
    float czz = a[9] * inv - mz * mz;

    float* o = out + (size_t)t * 12;
    o[0] = mx;  o[1] = my;  o[2] = mz;
    o[3] = cxx; o[4] = cxy; o[5] = cxz;
    o[6] = cxy; o[7] = cyy; o[8] = cyz;
    o[9] = cxz; o[10] = cyz; o[11] = czz;
}

// ---------------------------------------------------------------------------
extern "C" void kernel_launch(void* const* d_in, const int* in_sizes, int n_in,
                              void* d_out, int out_size) {
    const float* x    = (const float*)d_in[0];   // (B, N, 3) f32
    const int*   sidx = (const int*)d_in[1];     // (B, M) i32
    float*       out  = (float*)d_out;           // (B, M, 12) f32

    k_init<<<4, 256>>>();
    k_min<<<dim3(64, BB), 256>>>(x);
    k_mark<<<(BB * MM + 255) / 256, 256>>>(x, sidx);
    k_accum<<<(BB * NN + 255) / 256, 256>>>(x);
    k_out<<<(BB * MM + 255) / 256, 256>>>(x, sidx, out);
}